// round 11
// baseline (speedup 1.0000x reference)
#include <cuda_runtime.h>
#include <cuda_bf16.h>
#include <cstdint>

#define N_PTS 9216
#define DD 256
#define KROW 32            // stored row: 30 bf16 data dims + [-q,1]/[1,-q] slots (64B)
#define GRID_T 72
#define NT 2628            // 72*73/2 triangular tiles
#define ASTR 80            // smem row stride bytes (64B data + 16B pad, conflict-free LDSM)
#define THR (-8.75f)       // acc >= THR <=> d2hat_adj <= 17.5 (covers all d_full <= 4)
#define POSV ((float)(1.0 / 360.0))
#define NEGV ((float)(-0.5 / 8855.0))

__device__ __nv_bfloat16 g_XA[N_PTS * KROW];  // [x30, -q, 1]
__device__ __nv_bfloat16 g_XB[N_PTS * KROW];  // [x30, 1, -q]
__device__ float g_partials[NT];

// ------- prep: 4 threads/row; bf16-quantize dims 0..29; embed norms --------
__global__ void __launch_bounds__(256) prep_kernel(const float* __restrict__ images) {
    int tid = threadIdx.x;
    int row = (blockIdx.x * 256 + tid) >> 2;   // 4 threads per row
    int part = tid & 3;                        // dims [8*part, 8*part+8)
    const float4* src = (const float4*)(images + (size_t)row * DD + part * 8);
    float4 v0 = src[0], v1 = src[1];
    float vals[8] = {v0.x, v0.y, v0.z, v0.w, v1.x, v1.y, v1.z, v1.w};

    __nv_bfloat16 q[8];
    float s8 = 0.0f;
    int nd = (part == 3) ? 6 : 8;              // part 3: dims 24..29 only
    #pragma unroll
    for (int k = 0; k < 8; k++) {
        if (k < nd) {
            q[k] = __float2bfloat16_rn(vals[k]);
            float dq = __bfloat162float(q[k]);
            s8 = fmaf(dq, dq, s8);
        } else {
            q[k] = __float2bfloat16_rn(0.0f);
        }
    }
    // subset-norm reduce across the 4-lane group
    s8 += __shfl_xor_sync(0xffffffffu, s8, 1);
    s8 += __shfl_xor_sync(0xffffffffu, s8, 2);

    __nv_bfloat16 qn = __float2bfloat16_rn(-0.5f * s8);
    __nv_bfloat16 one = __float2bfloat16_rn(1.0f);

    // A variant: slots [30]=-q, [31]=1
    if (part == 3) { q[6] = qn; q[7] = one; }
    uint32_t w[4];
    #pragma unroll
    for (int k = 0; k < 4; k++) {
        __nv_bfloat162 p = __halves2bfloat162(q[2 * k], q[2 * k + 1]);
        w[k] = *(uint32_t*)&p;
    }
    *(uint4*)(g_XA + (size_t)row * KROW + part * 8) = make_uint4(w[0], w[1], w[2], w[3]);

    // B variant: slots [30]=1, [31]=-q
    if (part == 3) {
        q[6] = one; q[7] = qn;
        #pragma unroll
        for (int k = 3; k < 4; k++) {
            __nv_bfloat162 p = __halves2bfloat162(q[2 * k], q[2 * k + 1]);
            w[k] = *(uint32_t*)&p;
        }
    }
    *(uint4*)(g_XB + (size_t)row * KROW + part * 8) = make_uint4(w[0], w[1], w[2], w[3]);
}

// correction = sim(d2) + 1.0027, exact fp32, for d2 <= 16
__device__ __forceinline__ float corr_fn(float d2) {
    d2 = fmaxf(d2, 0.0f);
    float dist = (d2 > 0.0f) ? sqrtf(d2) : 0.0f;
    float t = 5.0f * (1.0f - dist);
    float sp = (t > 0.0f) ? (t + log1pf(expf(-t))) : log1pf(expf(t));
    return 0.4f * sp;
}
__device__ __forceinline__ float maskval(int i, int j) {
    int ci0 = i / 96, ci1 = i - ci0 * 96;
    int cj0 = j / 96, cj1 = j - cj0 * 96;
    int d0 = abs(ci0 - cj0); d0 = min(d0, 96 - d0);
    int d1 = abs(ci1 - cj1); d1 = min(d1, 96 - d1);
    return (d0 <= 9 && d1 <= 9) ? POSV : NEGV;
}

// -------- screening GEMM (K=32 bf16, norms embedded) + max-tree screen -----
__global__ void __launch_bounds__(256, 2)
pair_kernel(const float* __restrict__ images) {
    __shared__ uint8_t As[128 * ASTR];
    __shared__ uint8_t Bs[128 * ASTR];
    __shared__ float wsum[8];

    // triangular tile decode
    int t = blockIdx.x;
    int by = 0, rem = t;
    while (rem >= GRID_T - by) { rem -= GRID_T - by; by++; }
    int bx = by + rem;
    int i0 = by * 128, j0 = bx * 128;

    int tid  = threadIdx.x;
    int wid  = tid >> 5;
    int lane = tid & 31;
    int g  = lane >> 2;
    int tg = lane & 3;
    int wm = (wid >> 1) * 32;
    int wn = (wid & 1) * 64;

    // tile load: 128 rows x 64B each side; thread -> (row, 32B half)
    {
        int r = tid >> 1, h = (tid & 1) * 32;
        const uint8_t* sa = (const uint8_t*)(g_XA + (size_t)(i0 + r) * KROW) + h;
        const uint8_t* sb = (const uint8_t*)(g_XB + (size_t)(j0 + r) * KROW) + h;
        uint4 a0 = *(const uint4*)sa;
        uint4 a1 = *(const uint4*)(sa + 16);
        uint4 b0 = *(const uint4*)sb;
        uint4 b1 = *(const uint4*)(sb + 16);
        *(uint4*)(As + r * ASTR + h)      = a0;
        *(uint4*)(As + r * ASTR + h + 16) = a1;
        *(uint4*)(Bs + r * ASTR + h)      = b0;
        *(uint4*)(Bs + r * ASTR + h + 16) = b1;
    }
    __syncthreads();

    // ldmatrix addressing (byte offsets; proven geometry)
    int quad = lane >> 3, rw = lane & 7;
    uint32_t As_u, Bs_u;
    asm("{ .reg .u64 t; cvta.to.shared.u64 t, %1; cvt.u32.u64 %0, t; }" : "=r"(As_u) : "l"(As));
    asm("{ .reg .u64 t; cvta.to.shared.u64 t, %1; cvt.u32.u64 %0, t; }" : "=r"(Bs_u) : "l"(Bs));
    uint32_t aAddr = As_u + (uint32_t)((wm + rw + (quad & 1) * 8) * ASTR + (quad >> 1) * 16);
    uint32_t bAddr = Bs_u + (uint32_t)((wn + rw + ((quad >> 1) & 1) * 8) * ASTR + (quad & 1) * 16);

    float acc[2][8][4];
    #pragma unroll
    for (int a = 0; a < 2; a++)
        #pragma unroll
        for (int b = 0; b < 8; b++)
            #pragma unroll
            for (int c = 0; c < 4; c++) acc[a][b][c] = 0.0f;

    #pragma unroll
    for (int ksb = 0; ksb < 64; ksb += 32) {         // 2 k16 steps (32B each)
        uint32_t afr[2][4];
        #pragma unroll
        for (int mf = 0; mf < 2; mf++) {
            uint32_t ad = aAddr + (uint32_t)(mf * 16 * ASTR + ksb);
            asm volatile("ldmatrix.sync.aligned.m8n8.x4.shared.b16 {%0,%1,%2,%3}, [%4];"
                         : "=r"(afr[mf][0]), "=r"(afr[mf][1]),
                           "=r"(afr[mf][2]), "=r"(afr[mf][3]) : "r"(ad));
        }
        uint32_t bfr[8][2];
        #pragma unroll
        for (int p = 0; p < 4; p++) {
            uint32_t bd = bAddr + (uint32_t)(p * 16 * ASTR + ksb);
            asm volatile("ldmatrix.sync.aligned.m8n8.x4.shared.b16 {%0,%1,%2,%3}, [%4];"
                         : "=r"(bfr[2 * p][0]), "=r"(bfr[2 * p][1]),
                           "=r"(bfr[2 * p + 1][0]), "=r"(bfr[2 * p + 1][1]) : "r"(bd));
        }
        #pragma unroll
        for (int mf = 0; mf < 2; mf++)
            #pragma unroll
            for (int nf = 0; nf < 8; nf++) {
                asm volatile(
                    "mma.sync.aligned.m16n8k16.row.col.f32.bf16.bf16.f32 "
                    "{%0,%1,%2,%3}, {%4,%5,%6,%7}, {%8,%9}, {%0,%1,%2,%3};\n"
                    : "+f"(acc[mf][nf][0]), "+f"(acc[mf][nf][1]),
                      "+f"(acc[mf][nf][2]), "+f"(acc[mf][nf][3])
                    : "r"(afr[mf][0]), "r"(afr[mf][1]),
                      "r"(afr[mf][2]), "r"(afr[mf][3]),
                      "r"(bfr[nf][0]), "r"(bfr[nf][1]));
            }
    }

    // ---- epilogue: acc ~= -d2hat/2; screen = ILP max tree + ballot ----
    float local = 0.0f;
    float m16[16];
    #pragma unroll
    for (int mf = 0; mf < 2; mf++)
        #pragma unroll
        for (int nf = 0; nf < 8; nf++)
            m16[mf * 8 + nf] = fmaxf(fmaxf(acc[mf][nf][0], acc[mf][nf][1]),
                                     fmaxf(acc[mf][nf][2], acc[mf][nf][3]));
    #pragma unroll
    for (int s = 8; s > 0; s >>= 1)
        #pragma unroll
        for (int k = 0; k < 8; k++)
            if (k < s) m16[k] = fmaxf(m16[k], m16[k + s]);

    if (__any_sync(0xffffffffu, m16[0] >= THR)) {    // ~only diagonal tiles + ~1K pairs
        #pragma unroll 1
        for (int mf = 0; mf < 2; mf++) {
            #pragma unroll 1
            for (int nf = 0; nf < 8; nf++) {
                #pragma unroll
                for (int q = 0; q < 4; q++) {
                    if (acc[mf][nf][q] >= THR) {
                        int i = i0 + wm + mf * 16 + g + (q >> 1) * 8;
                        int j = j0 + wn + nf * 8 + 2 * tg + (q & 1);
                        if (i < j) {                 // count once, weight x2
                            const float4* xa = (const float4*)(images + (size_t)i * DD);
                            const float4* xb = (const float4*)(images + (size_t)j * DD);
                            float sqi = 0.0f, sqj = 0.0f, dot = 0.0f;
                            #pragma unroll 8
                            for (int u = 0; u < 64; u++) {
                                float4 a = xa[u], b = xb[u];
                                sqi = fmaf(a.x, a.x, sqi); sqi = fmaf(a.y, a.y, sqi);
                                sqi = fmaf(a.z, a.z, sqi); sqi = fmaf(a.w, a.w, sqi);
                                sqj = fmaf(b.x, b.x, sqj); sqj = fmaf(b.y, b.y, sqj);
                                sqj = fmaf(b.z, b.z, sqj); sqj = fmaf(b.w, b.w, sqj);
                                dot = fmaf(a.x, b.x, dot); dot = fmaf(a.y, b.y, dot);
                                dot = fmaf(a.z, b.z, dot); dot = fmaf(a.w, b.w, dot);
                            }
                            float d2 = fmaxf(sqi + sqj - 2.0f * dot, 0.0f);
                            if (d2 <= 16.0f)
                                local = fmaf(2.0f * corr_fn(d2), maskval(i, j), local);
                        }
                    }
                }
            }
        }
    }

    #pragma unroll
    for (int o = 16; o > 0; o >>= 1) local += __shfl_xor_sync(0xffffffffu, local, o);
    if (lane == 0) wsum[wid] = local;
    __syncthreads();
    if (tid == 0) {
        float s = 0.0f;
        #pragma unroll
        for (int w = 0; w < 8; w++) s += wsum[w];
        g_partials[blockIdx.x] = s;
    }
}

// ---------------- final reduce + closed-form base term ---------------------
__global__ void reduce_kernel(float* __restrict__ out) {
    int t = threadIdx.x;  // 256
    float s = 0.0f;
    for (int i = t; i < NT; i += 256) s += g_partials[i];
    #pragma unroll
    for (int o = 16; o > 0; o >>= 1) s += __shfl_xor_sync(0xffffffffu, s, o);
    __shared__ float ws[8];
    if ((t & 31) == 0) ws[t >> 5] = s;
    __syncthreads();
    if (t == 0) {
        float tot = 0.0f;
        #pragma unroll
        for (int w = 0; w < 8; w++) tot += ws[w];
        // off-diag sim == -1.0027f exactly; sum(mask) = N*(360*POSV + 8855*NEGV)
        double masksum = 9216.0 * (360.0 * (double)POSV + 8855.0 * (double)NEGV);
        double base = (double)(-1.0027f) * masksum;
        out[0] = (float)(((double)tot + base) / 9216.0);
    }
}

extern "C" void kernel_launch(void* const* d_in, const int* in_sizes, int n_in,
                              void* d_out, int out_size) {
    const float* images = (const float*)d_in[0];   // [9216,1,16,16] fp32
    (void)in_sizes; (void)n_in;
    prep_kernel<<<N_PTS * 4 / 256, 256>>>(images);
    pair_kernel<<<NT, 256>>>(images);
    reduce_kernel<<<1, 256>>>((float*)d_out);
}

// round 12
// speedup vs baseline: 1.6927x; 1.6927x over previous
#include <cuda_runtime.h>
#include <cuda_bf16.h>
#include <cuda_fp8.h>
#include <cstdint>

#define N_PTS 9216
#define DD 256
#define KSUB 64            // screening subset: dims 0..63 (d2_full >= d2_sub, strict)
#define NBY 72             // 128-row i tiles
#define NJX 144            // 64-col j tiles
#define NT 5256            // sum over by of (144 - 2*by)
#define ASTR 80            // smem row stride bytes (64B data + 16B pad, conflict-free LDSM)
#define POSV ((float)(1.0 / 360.0))
#define NEGV ((float)(-0.5 / 8855.0))

__device__ uint8_t g_X8[N_PTS * KSUB];     // e4m3 of first 64 dims
__device__ float g_sq[N_PTS];              // full 256-dim fp32 norms (rescue)
__device__ float g_sq8[N_PTS];             // subset norms of DEQUANTIZED values (exact screen)
__device__ float g_partials[NT];

// ---------------- prep: quantize 64 dims + both norms (R5 proven) ----------
__global__ void __launch_bounds__(256) prep_kernel(const float* __restrict__ images) {
    int wid = threadIdx.x >> 5, lane = threadIdx.x & 31;
    int row = blockIdx.x * 16 + wid * 2;
    const float4* s0 = (const float4*)(images + (size_t)row * DD);
    const float4* s1 = (const float4*)(images + (size_t)(row + 1) * DD);
    float4 a0 = s0[lane * 2], a1 = s0[lane * 2 + 1];
    float4 b0 = s1[lane * 2], b1 = s1[lane * 2 + 1];

    float na = a0.x*a0.x + a0.y*a0.y + a0.z*a0.z + a0.w*a0.w
             + a1.x*a1.x + a1.y*a1.y + a1.z*a1.z + a1.w*a1.w;
    float nb = b0.x*b0.x + b0.y*b0.y + b0.z*b0.z + b0.w*b0.w
             + b1.x*b1.x + b1.y*b1.y + b1.z*b1.z + b1.w*b1.w;
    #pragma unroll
    for (int o = 16; o > 0; o >>= 1) {
        na += __shfl_xor_sync(0xffffffffu, na, o);
        nb += __shfl_xor_sync(0xffffffffu, nb, o);
    }
    if (lane == 0) { g_sq[row] = na; g_sq[row + 1] = nb; }

    float s8a = 0.0f, s8b = 0.0f;
    if (lane < 8) {
        float va[8] = {a0.x, a0.y, a0.z, a0.w, a1.x, a1.y, a1.z, a1.w};
        float vb[8] = {b0.x, b0.y, b0.z, b0.w, b1.x, b1.y, b1.z, b1.w};
        uint32_t qa[2] = {0, 0}, qb[2] = {0, 0};
        #pragma unroll
        for (int k = 0; k < 8; k++) {
            uint8_t ea = __nv_cvt_float_to_fp8(va[k], __NV_SATFINITE, __NV_E4M3);
            uint8_t eb = __nv_cvt_float_to_fp8(vb[k], __NV_SATFINITE, __NV_E4M3);
            qa[k >> 2] |= (uint32_t)ea << ((k & 3) * 8);
            qb[k >> 2] |= (uint32_t)eb << ((k & 3) * 8);
            float da = __half2float(__nv_cvt_fp8_to_halfraw(ea, __NV_E4M3));
            float db = __half2float(__nv_cvt_fp8_to_halfraw(eb, __NV_E4M3));
            s8a = fmaf(da, da, s8a);
            s8b = fmaf(db, db, s8b);
        }
        *(uint2*)(g_X8 + (size_t)row * KSUB + lane * 8) = make_uint2(qa[0], qa[1]);
        *(uint2*)(g_X8 + (size_t)(row + 1) * KSUB + lane * 8) = make_uint2(qb[0], qb[1]);
    }
    #pragma unroll
    for (int o = 16; o > 0; o >>= 1) {
        s8a += __shfl_xor_sync(0xffffffffu, s8a, o);
        s8b += __shfl_xor_sync(0xffffffffu, s8b, o);
    }
    if (lane == 0) { g_sq8[row] = s8a; g_sq8[row + 1] = s8b; }
}

// correction = sim(d2) + 1.0027, exact fp32, for d2 <= 16
__device__ __forceinline__ float corr_fn(float d2) {
    d2 = fmaxf(d2, 0.0f);
    float dist = (d2 > 0.0f) ? sqrtf(d2) : 0.0f;
    float t = 5.0f * (1.0f - dist);
    float sp = (t > 0.0f) ? (t + log1pf(expf(-t))) : log1pf(expf(t));
    return 0.4f * sp;
}
__device__ __forceinline__ float maskval(int i, int j) {
    int ci0 = i / 96, ci1 = i - ci0 * 96;
    int cj0 = j / 96, cj1 = j - cj0 * 96;
    int d0 = abs(ci0 - cj0); d0 = min(d0, 96 - d0);
    int d1 = abs(ci1 - cj1); d1 = min(d1, 96 - d1);
    return (d0 <= 9 && d1 <= 9) ? POSV : NEGV;
}

// -------- 128x64 screening GEMM (K=64 fp8) + exact rescue, 3 CTAs/SM -------
__global__ void __launch_bounds__(256, 3)
pair_kernel(const float* __restrict__ images) {
    __shared__ uint8_t As[128 * ASTR];
    __shared__ uint8_t Bs[64 * ASTR];
    __shared__ float sSq8I[128];
    __shared__ float sSq8J[64];
    __shared__ float wsum[8];

    // tile decode over (by: 128-row, jx: 64-col), jx >= 2*by
    int t = blockIdx.x;
    int by = 0, rem = t;
    while (rem >= NJX - 2 * by) { rem -= NJX - 2 * by; by++; }
    int jx = 2 * by + rem;
    int i0 = by * 128, j0 = jx * 64;

    int tid  = threadIdx.x;
    int wid  = tid >> 5;
    int lane = tid & 31;
    int g  = lane >> 2;
    int tg = lane & 3;
    int wm = (wid >> 1) * 32;   // 4 m-warps: 0/32/64/96
    int wn = (wid & 1) * 32;    // 2 n-warps: 0/32

    if (tid < 128)      sSq8I[tid] = g_sq8[i0 + tid];
    else if (tid < 192) sSq8J[tid - 128] = g_sq8[j0 + (tid - 128)];

    // tile loads: A 128 rows x 64B (all threads), B 64 rows x 64B (tid<128)
    {
        int r = tid >> 1, h = (tid & 1) * 32;
        const uint8_t* sa = g_X8 + (size_t)(i0 + r) * KSUB + h;
        uint4 a0 = *(const uint4*)sa;
        uint4 a1 = *(const uint4*)(sa + 16);
        *(uint4*)(As + r * ASTR + h)      = a0;
        *(uint4*)(As + r * ASTR + h + 16) = a1;
        if (tid < 128) {
            const uint8_t* sb = g_X8 + (size_t)(j0 + r) * KSUB + h;
            uint4 b0 = *(const uint4*)sb;
            uint4 b1 = *(const uint4*)(sb + 16);
            *(uint4*)(Bs + r * ASTR + h)      = b0;
            *(uint4*)(Bs + r * ASTR + h + 16) = b1;
        }
    }
    __syncthreads();

    // ldmatrix addressing (proven geometry)
    int quad = lane >> 3, rw = lane & 7;
    uint32_t As_u, Bs_u;
    asm("{ .reg .u64 t; cvta.to.shared.u64 t, %1; cvt.u32.u64 %0, t; }" : "=r"(As_u) : "l"(As));
    asm("{ .reg .u64 t; cvta.to.shared.u64 t, %1; cvt.u32.u64 %0, t; }" : "=r"(Bs_u) : "l"(Bs));
    uint32_t aAddr = As_u + (uint32_t)((wm + rw + (quad & 1) * 8) * ASTR + (quad >> 1) * 16);
    uint32_t bAddr = Bs_u + (uint32_t)((wn + rw + ((quad >> 1) & 1) * 8) * ASTR + (quad & 1) * 16);

    float acc[2][4][4];
    #pragma unroll
    for (int a = 0; a < 2; a++)
        #pragma unroll
        for (int b = 0; b < 4; b++)
            #pragma unroll
            for (int c = 0; c < 4; c++) acc[a][b][c] = 0.0f;

    #pragma unroll
    for (int ksb = 0; ksb < KSUB; ksb += 32) {       // 2 k32 steps
        uint32_t afr[2][4];
        #pragma unroll
        for (int mf = 0; mf < 2; mf++) {
            uint32_t ad = aAddr + (uint32_t)(mf * 16 * ASTR + ksb);
            asm volatile("ldmatrix.sync.aligned.m8n8.x4.shared.b16 {%0,%1,%2,%3}, [%4];"
                         : "=r"(afr[mf][0]), "=r"(afr[mf][1]),
                           "=r"(afr[mf][2]), "=r"(afr[mf][3]) : "r"(ad));
        }
        uint32_t bfr[4][2];
        #pragma unroll
        for (int p = 0; p < 2; p++) {
            uint32_t bd = bAddr + (uint32_t)(p * 16 * ASTR + ksb);
            asm volatile("ldmatrix.sync.aligned.m8n8.x4.shared.b16 {%0,%1,%2,%3}, [%4];"
                         : "=r"(bfr[2 * p][0]), "=r"(bfr[2 * p][1]),
                           "=r"(bfr[2 * p + 1][0]), "=r"(bfr[2 * p + 1][1]) : "r"(bd));
        }
        #pragma unroll
        for (int mf = 0; mf < 2; mf++)
            #pragma unroll
            for (int nf = 0; nf < 4; nf++) {
                asm volatile(
                    "mma.sync.aligned.m16n8k32.row.col.f32.e4m3.e4m3.f32 "
                    "{%0,%1,%2,%3}, {%4,%5,%6,%7}, {%8,%9}, {%0,%1,%2,%3};\n"
                    : "+f"(acc[mf][nf][0]), "+f"(acc[mf][nf][1]),
                      "+f"(acc[mf][nf][2]), "+f"(acc[mf][nf][3])
                    : "r"(afr[mf][0]), "r"(afr[mf][1]),
                      "r"(afr[mf][2]), "r"(afr[mf][3]),
                      "r"(bfr[nf][0]), "r"(bfr[nf][1]));
            }
    }

    // ---- epilogue: exact quantized-space screen, d2hat <= 32 => rescue ----
    // d2_full >= d2_sub(true); quant slack: d<=4 => d2hat <= 29.2 < 32.
    // P(trigger) ~ 1e-8 per pair => fires only on diagonal fragments.
    float local = 0.0f;
    #pragma unroll
    for (int mf = 0; mf < 2; mf++) {
        int r0 = wm + mf * 16 + g;
        float sqa = sSq8I[r0];
        float sqb = sSq8I[r0 + 8];
        #pragma unroll
        for (int nf = 0; nf < 4; nf++) {
            int cl = wn + nf * 8 + 2 * tg;
            float sj0 = sSq8J[cl];
            float sj1 = sSq8J[cl + 1];
            float d00 = fmaf(-2.0f, acc[mf][nf][0], sqa + sj0);
            float d01 = fmaf(-2.0f, acc[mf][nf][1], sqa + sj1);
            float d10 = fmaf(-2.0f, acc[mf][nf][2], sqb + sj0);
            float d11 = fmaf(-2.0f, acc[mf][nf][3], sqb + sj1);
            float mn = fminf(fminf(d00, d01), fminf(d10, d11));
            if (mn <= 32.0f) {          // ~only diagonal fragments
                #pragma unroll
                for (int q = 0; q < 4; q++) {
                    float d2f = (q == 0) ? d00 : (q == 1) ? d01 : (q == 2) ? d10 : d11;
                    if (d2f <= 32.0f) {
                        int i = i0 + r0 + (q >> 1) * 8;
                        int j = j0 + cl + (q & 1);
                        if (i < j) {    // count once, weight x2 (symmetry)
                            const float4* xa = (const float4*)(images + (size_t)i * DD);
                            const float4* xb = (const float4*)(images + (size_t)j * DD);
                            float dot = 0.0f;
                            #pragma unroll 8
                            for (int u = 0; u < 64; u++) {
                                float4 a = xa[u], b = xb[u];
                                dot = fmaf(a.x, b.x, dot); dot = fmaf(a.y, b.y, dot);
                                dot = fmaf(a.z, b.z, dot); dot = fmaf(a.w, b.w, dot);
                            }
                            float d2 = fmaxf(g_sq[i] + g_sq[j] - 2.0f * dot, 0.0f);
                            if (d2 <= 16.0f)
                                local = fmaf(2.0f * corr_fn(d2), maskval(i, j), local);
                        }
                    }
                }
            }
        }
    }

    #pragma unroll
    for (int o = 16; o > 0; o >>= 1) local += __shfl_xor_sync(0xffffffffu, local, o);
    if (lane == 0) wsum[wid] = local;
    __syncthreads();
    if (tid == 0) {
        float s = 0.0f;
        #pragma unroll
        for (int w = 0; w < 8; w++) s += wsum[w];
        g_partials[blockIdx.x] = s;
    }
}

// ---------------- final reduce + closed-form base term ---------------------
__global__ void reduce_kernel(float* __restrict__ out) {
    int t = threadIdx.x;  // 256
    float s = 0.0f;
    for (int i = t; i < NT; i += 256) s += g_partials[i];
    #pragma unroll
    for (int o = 16; o > 0; o >>= 1) s += __shfl_xor_sync(0xffffffffu, s, o);
    __shared__ float ws[8];
    if ((t & 31) == 0) ws[t >> 5] = s;
    __syncthreads();
    if (t == 0) {
        float tot = 0.0f;
        #pragma unroll
        for (int w = 0; w < 8; w++) tot += ws[w];
        // off-diag sim == -1.0027f exactly; sum(mask) = N*(360*POSV + 8855*NEGV)
        double masksum = 9216.0 * (360.0 * (double)POSV + 8855.0 * (double)NEGV);
        double base = (double)(-1.0027f) * masksum;
        out[0] = (float)(((double)tot + base) / 9216.0);
    }
}

extern "C" void kernel_launch(void* const* d_in, const int* in_sizes, int n_in,
                              void* d_out, int out_size) {
    const float* images = (const float*)d_in[0];   // [9216,1,16,16] fp32
    (void)in_sizes; (void)n_in;
    prep_kernel<<<N_PTS / 16, 256>>>(images);
    pair_kernel<<<NT, 256>>>(images);
    reduce_kernel<<<1, 256>>>((float*)d_out);
}

// round 13
// speedup vs baseline: 1.8358x; 1.0846x over previous
#include <cuda_runtime.h>
#include <cuda_bf16.h>
#include <cuda_fp8.h>
#include <cstdint>

#define N_PTS 9216
#define DD 256
#define KSUB 64            // screening subset: dims 0..63 (d2_full >= d2_sub, strict)
#define GRID_T 72
#define NT 2628            // 72*73/2 triangular tiles
#define ASTR 80            // smem row stride bytes (64B data + 16B pad, conflict-free LDSM)
#define POSV ((float)(1.0 / 360.0))
#define NEGV ((float)(-0.5 / 8855.0))

__device__ uint8_t g_X8[N_PTS * KSUB];     // e4m3 of first 64 dims
__device__ float g_sq8[N_PTS];             // subset norms of DEQUANTIZED values (exact screen)
__device__ float g_partials[NT];

// ------- prep: 8 threads/row, dims 0..63 ONLY (2.4 MB read) ----------------
__global__ void __launch_bounds__(256) prep_kernel(const float* __restrict__ images) {
    int tid = threadIdx.x;
    int row = (blockIdx.x * 256 + tid) >> 3;   // 8 threads per row
    int p = tid & 7;                           // dims [8p, 8p+8)
    const float4* src = (const float4*)(images + (size_t)row * DD + p * 8);
    float4 v0 = src[0], v1 = src[1];
    float vals[8] = {v0.x, v0.y, v0.z, v0.w, v1.x, v1.y, v1.z, v1.w};

    uint32_t q[2] = {0, 0};
    float s8 = 0.0f;
    #pragma unroll
    for (int k = 0; k < 8; k++) {
        uint8_t e = __nv_cvt_float_to_fp8(vals[k], __NV_SATFINITE, __NV_E4M3);
        q[k >> 2] |= (uint32_t)e << ((k & 3) * 8);
        float dq = __half2float(__nv_cvt_fp8_to_halfraw(e, __NV_E4M3));
        s8 = fmaf(dq, dq, s8);
    }
    *(uint2*)(g_X8 + (size_t)row * KSUB + p * 8) = make_uint2(q[0], q[1]);

    // reduce subset norm across the 8-lane row group
    s8 += __shfl_xor_sync(0xffffffffu, s8, 1);
    s8 += __shfl_xor_sync(0xffffffffu, s8, 2);
    s8 += __shfl_xor_sync(0xffffffffu, s8, 4);
    if (p == 0) g_sq8[row] = s8;
}

// correction = sim(d2) + 1.0027, exact fp32, for d2 <= 16
__device__ __forceinline__ float corr_fn(float d2) {
    d2 = fmaxf(d2, 0.0f);
    float dist = (d2 > 0.0f) ? sqrtf(d2) : 0.0f;
    float t = 5.0f * (1.0f - dist);
    float sp = (t > 0.0f) ? (t + log1pf(expf(-t))) : log1pf(expf(t));
    return 0.4f * sp;
}
__device__ __forceinline__ float maskval(int i, int j) {
    int ci0 = i / 96, ci1 = i - ci0 * 96;
    int cj0 = j / 96, cj1 = j - cj0 * 96;
    int d0 = abs(ci0 - cj0); d0 = min(d0, 96 - d0);
    int d1 = abs(ci1 - cj1); d1 = min(d1, 96 - d1);
    return (d0 <= 9 && d1 <= 9) ? POSV : NEGV;
}

// ---------------- screening GEMM (K=64 fp8) + exact rescue (R5 proven) -----
__global__ void __launch_bounds__(256, 2)
pair_kernel(const float* __restrict__ images) {
    __shared__ uint8_t As[128 * ASTR];
    __shared__ uint8_t Bs[128 * ASTR];
    __shared__ float sSq8I[128];
    __shared__ float sSq8J[128];
    __shared__ float wsum[8];

    // triangular tile decode
    int t = blockIdx.x;
    int by = 0, rem = t;
    while (rem >= GRID_T - by) { rem -= GRID_T - by; by++; }
    int bx = by + rem;
    int i0 = by * 128, j0 = bx * 128;

    int tid  = threadIdx.x;
    int wid  = tid >> 5;
    int lane = tid & 31;
    int g  = lane >> 2;
    int tg = lane & 3;
    int wm = (wid >> 1) * 32;
    int wn = (wid & 1) * 64;

    if (tid < 128) sSq8I[tid] = g_sq8[i0 + tid];
    else           sSq8J[tid - 128] = g_sq8[j0 + (tid - 128)];

    // tile load: 128 rows x 64B each side; thread -> (row, 32B half)
    {
        int r = tid >> 1, h = (tid & 1) * 32;
        const uint8_t* sa = g_X8 + (size_t)(i0 + r) * KSUB + h;
        const uint8_t* sb = g_X8 + (size_t)(j0 + r) * KSUB + h;
        uint4 a0 = *(const uint4*)sa;
        uint4 a1 = *(const uint4*)(sa + 16);
        uint4 b0 = *(const uint4*)sb;
        uint4 b1 = *(const uint4*)(sb + 16);
        *(uint4*)(As + r * ASTR + h)      = a0;
        *(uint4*)(As + r * ASTR + h + 16) = a1;
        *(uint4*)(Bs + r * ASTR + h)      = b0;
        *(uint4*)(Bs + r * ASTR + h + 16) = b1;
    }
    __syncthreads();

    // ldmatrix addressing (proven geometry)
    int quad = lane >> 3, rw = lane & 7;
    uint32_t As_u, Bs_u;
    asm("{ .reg .u64 t; cvta.to.shared.u64 t, %1; cvt.u32.u64 %0, t; }" : "=r"(As_u) : "l"(As));
    asm("{ .reg .u64 t; cvta.to.shared.u64 t, %1; cvt.u32.u64 %0, t; }" : "=r"(Bs_u) : "l"(Bs));
    uint32_t aAddr = As_u + (uint32_t)((wm + rw + (quad & 1) * 8) * ASTR + (quad >> 1) * 16);
    uint32_t bAddr = Bs_u + (uint32_t)((wn + rw + ((quad >> 1) & 1) * 8) * ASTR + (quad & 1) * 16);

    float acc[2][8][4];
    #pragma unroll
    for (int a = 0; a < 2; a++)
        #pragma unroll
        for (int b = 0; b < 8; b++)
            #pragma unroll
            for (int c = 0; c < 4; c++) acc[a][b][c] = 0.0f;

    #pragma unroll
    for (int ksb = 0; ksb < KSUB; ksb += 32) {       // 2 k32 steps
        uint32_t afr[2][4];
        #pragma unroll
        for (int mf = 0; mf < 2; mf++) {
            uint32_t ad = aAddr + (uint32_t)(mf * 16 * ASTR + ksb);
            asm volatile("ldmatrix.sync.aligned.m8n8.x4.shared.b16 {%0,%1,%2,%3}, [%4];"
                         : "=r"(afr[mf][0]), "=r"(afr[mf][1]),
                           "=r"(afr[mf][2]), "=r"(afr[mf][3]) : "r"(ad));
        }
        uint32_t bfr[8][2];
        #pragma unroll
        for (int p = 0; p < 4; p++) {
            uint32_t bd = bAddr + (uint32_t)(p * 16 * ASTR + ksb);
            asm volatile("ldmatrix.sync.aligned.m8n8.x4.shared.b16 {%0,%1,%2,%3}, [%4];"
                         : "=r"(bfr[2 * p][0]), "=r"(bfr[2 * p][1]),
                           "=r"(bfr[2 * p + 1][0]), "=r"(bfr[2 * p + 1][1]) : "r"(bd));
        }
        #pragma unroll
        for (int mf = 0; mf < 2; mf++)
            #pragma unroll
            for (int nf = 0; nf < 8; nf++) {
                asm volatile(
                    "mma.sync.aligned.m16n8k32.row.col.f32.e4m3.e4m3.f32 "
                    "{%0,%1,%2,%3}, {%4,%5,%6,%7}, {%8,%9}, {%0,%1,%2,%3};\n"
                    : "+f"(acc[mf][nf][0]), "+f"(acc[mf][nf][1]),
                      "+f"(acc[mf][nf][2]), "+f"(acc[mf][nf][3])
                    : "r"(afr[mf][0]), "r"(afr[mf][1]),
                      "r"(afr[mf][2]), "r"(afr[mf][3]),
                      "r"(bfr[nf][0]), "r"(bfr[nf][1]));
            }
    }

    // ---- epilogue: exact quantized-space screen, d2hat <= 32 => rescue ----
    // d2_full >= d2_sub(true); quant slack: d<=4 => d2hat <= 29.2 < 32.
    float local = 0.0f;
    #pragma unroll
    for (int mf = 0; mf < 2; mf++) {
        int r0 = wm + mf * 16 + g;
        float sqa = sSq8I[r0];
        float sqb = sSq8I[r0 + 8];
        #pragma unroll
        for (int nf = 0; nf < 8; nf++) {
            int cl = wn + nf * 8 + 2 * tg;
            float sj0 = sSq8J[cl];
            float sj1 = sSq8J[cl + 1];
            float d00 = fmaf(-2.0f, acc[mf][nf][0], sqa + sj0);
            float d01 = fmaf(-2.0f, acc[mf][nf][1], sqa + sj1);
            float d10 = fmaf(-2.0f, acc[mf][nf][2], sqb + sj0);
            float d11 = fmaf(-2.0f, acc[mf][nf][3], sqb + sj1);
            float mn = fminf(fminf(d00, d01), fminf(d10, d11));
            if (mn <= 32.0f) {          // ~only diagonal fragments trigger
                #pragma unroll
                for (int q = 0; q < 4; q++) {
                    float d2f = (q == 0) ? d00 : (q == 1) ? d01 : (q == 2) ? d10 : d11;
                    if (d2f <= 32.0f) {
                        int i = i0 + r0 + (q >> 1) * 8;
                        int j = j0 + cl + (q & 1);
                        if (i < j) {    // count once, weight x2 (symmetry)
                            const float4* xa = (const float4*)(images + (size_t)i * DD);
                            const float4* xb = (const float4*)(images + (size_t)j * DD);
                            float sqi = 0.0f, sqj = 0.0f, dot = 0.0f;
                            #pragma unroll 8
                            for (int u = 0; u < 64; u++) {
                                float4 a = xa[u], b = xb[u];
                                sqi = fmaf(a.x, a.x, sqi); sqi = fmaf(a.y, a.y, sqi);
                                sqi = fmaf(a.z, a.z, sqi); sqi = fmaf(a.w, a.w, sqi);
                                sqj = fmaf(b.x, b.x, sqj); sqj = fmaf(b.y, b.y, sqj);
                                sqj = fmaf(b.z, b.z, sqj); sqj = fmaf(b.w, b.w, sqj);
                                dot = fmaf(a.x, b.x, dot); dot = fmaf(a.y, b.y, dot);
                                dot = fmaf(a.z, b.z, dot); dot = fmaf(a.w, b.w, dot);
                            }
                            float d2 = fmaxf(sqi + sqj - 2.0f * dot, 0.0f);
                            if (d2 <= 16.0f)
                                local = fmaf(2.0f * corr_fn(d2), maskval(i, j), local);
                        }
                    }
                }
            }
        }
    }

    #pragma unroll
    for (int o = 16; o > 0; o >>= 1) local += __shfl_xor_sync(0xffffffffu, local, o);
    if (lane == 0) wsum[wid] = local;
    __syncthreads();
    if (tid == 0) {
        float s = 0.0f;
        #pragma unroll
        for (int w = 0; w < 8; w++) s += wsum[w];
        g_partials[blockIdx.x] = s;
    }
}

// ---------------- final reduce + closed-form base term ---------------------
__global__ void reduce_kernel(float* __restrict__ out) {
    int t = threadIdx.x;  // 256
    float s = 0.0f;
    for (int i = t; i < NT; i += 256) s += g_partials[i];
    #pragma unroll
    for (int o = 16; o > 0; o >>= 1) s += __shfl_xor_sync(0xffffffffu, s, o);
    __shared__ float ws[8];
    if ((t & 31) == 0) ws[t >> 5] = s;
    __syncthreads();
    if (t == 0) {
        float tot = 0.0f;
        #pragma unroll
        for (int w = 0; w < 8; w++) tot += ws[w];
        // off-diag sim == -1.0027f exactly; sum(mask) = N*(360*POSV + 8855*NEGV)
        double masksum = 9216.0 * (360.0 * (double)POSV + 8855.0 * (double)NEGV);
        double base = (double)(-1.0027f) * masksum;
        out[0] = (float)(((double)tot + base) / 9216.0);
    }
}

extern "C" void kernel_launch(void* const* d_in, const int* in_sizes, int n_in,
                              void* d_out, int out_size) {
    const float* images = (const float*)d_in[0];   // [9216,1,16,16] fp32
    (void)in_sizes; (void)n_in;
    prep_kernel<<<N_PTS * 8 / 256, 256>>>(images);
    pair_kernel<<<NT, 256>>>(images);
    reduce_kernel<<<1, 256>>>((float*)d_out);
}